// round 12
// baseline (speedup 1.0000x reference)
#include <cuda_runtime.h>
#include <math.h>

#define D_PTS   2562
#define D_PAD   2624          // 41*64
#define F_BINS  513
#define P_PAIRS 36
#define KDEG    32
#define PK      (P_PAIRS*KDEG)   // 1152
#define BT_N    1000
#define BT_PAD  1024
#define YP      D_PAD
#define TAU_M   4.67

// ---------------- packed f32x2 / async helpers ---------------------------------
__device__ __forceinline__ void fma2(unsigned long long& d,
                                     unsigned long long a, unsigned long long b) {
    asm("fma.rn.f32x2 %0, %1, %2, %0;" : "+l"(d) : "l"(a), "l"(b));
}
__device__ __forceinline__ float plo(unsigned long long v) {
    return __uint_as_float((unsigned)v);
}
__device__ __forceinline__ float phi(unsigned long long v) {
    return __uint_as_float((unsigned)(v >> 32));
}
#define PACKDUP(out, v) asm("mov.b64 %0, {%1, %1};" : "=l"(out) : "f"(v))
__device__ __forceinline__ void cp16(const void* smem, const void* gmem) {
    unsigned sa = (unsigned)__cvta_generic_to_shared(smem);
    asm volatile("cp.async.ca.shared.global [%0], [%1], 16;" :: "r"(sa), "l"(gmem));
}
#define CP_COMMIT()  asm volatile("cp.async.commit_group;" ::: "memory")
#define CP_WAIT(n)   asm volatile("cp.async.wait_group %0;" :: "n"(n) : "memory")

// ---------------- scratch (K-major transposed operands) ------------------------
__device__ float2 g_CS[F_BINS*KDEG];           // (ac,as) packed per (f,k)
__device__ float  g_Mt[(size_t)PK*BT_PAD];     // moments   [k][bt]
__device__ float  g_Wt[(size_t)PK*D_PAD];      // Cheb vals [k][d]
__device__ float  g_Y[(size_t)BT_PAD*YP];      // scores    [bt][d]

__device__ const int c_i0[P_PAIRS] = {0,0,0,0,0,0,0,0, 1,1,1,1,1,1,1, 2,2,2,2,2,2,
                                      3,3,3,3,3, 4,4,4,4, 5,5,5, 6,6, 7};
__device__ const int c_i1[P_PAIRS] = {0,1,2,3,4,5,6,7, 1,2,3,4,5,6,7, 2,3,4,5,6,7,
                                      3,4,5,6,7, 4,5,6,7, 5,6,7, 6,7, 7};

// ---------------- Stage A1: Chebyshev coefficients (fp64 DCT) ------------------
__global__ void k_coeff() {
    __shared__ double vc[64], vs[64];
    const double PI = 3.141592653589793238462643;
    int f = blockIdx.x;
    int n = threadIdx.x;
    double c = (2.0 * PI * (double)f / 1024.0) * (double)TAU_M;
    double theta = PI * (n + 0.5) / 64.0;
    double x = cos(theta);
    double sn, cn;
    sincos(c * x, &sn, &cn);
    vc[n] = cn; vs[n] = sn;
    __syncthreads();
    int k = threadIdx.x;
    if (k < KDEG) {
        double delta = (PI / 64.0) * (double)k;
        double c0 = cos(0.5 * delta);
        double c1 = cos(1.5 * delta);
        double mult = 2.0 * cos(delta);
        double sc = vc[0]*c0 + vc[1]*c1;
        double ss = vs[0]*c0 + vs[1]*c1;
        double cp = c0, cc = c1;
        for (int nn = 2; nn < 64; nn++) {
            double cnx = mult*cc - cp;
            sc += vc[nn]*cnx; ss += vs[nn]*cnx;
            cp = cc; cc = cnx;
        }
        double scale = (k == 0 ? 1.0 : 2.0) / 64.0;
        g_CS[f*KDEG + k] = make_float2((float)(sc*scale), (float)(ss*scale));
    }
}

// ---------------- Stage A2: T_k table, K-major (one thread per d) --------------
// Writes g_Wt[(p*32+kk)][d] — coalesced across the warp (consecutive d).
__global__ void k_w2t(const float* __restrict__ taus, int D) {
    int d = blockIdx.x * blockDim.x + threadIdx.x;
    if (d >= D_PAD) return;
    float t[8];
#pragma unroll
    for (int i = 0; i < 8; i++) t[i] = (d < D) ? taus[d*8 + i] : 0.0f;
    for (int p = 0; p < P_PAIRS; p++) {
        float u = (t[c_i0[p]] - t[c_i1[p]]) * (float)(1.0 / TAU_M);
        float* w = g_Wt + (size_t)(p * KDEG) * D_PAD + d;
        float tp = 1.0f, tc = u;
        w[0] = 1.0f;
        w[(size_t)D_PAD] = u;
        float u2 = 2.0f * u;
#pragma unroll
        for (int kk = 2; kk < KDEG; kk++) {
            float tn = fmaf(u2, tc, -tp);
            w[(size_t)kk * D_PAD] = tn;
            tp = tc; tc = tn;
        }
    }
}

// ---------------- Stage B: PHAT normalize + moments (pipelined, f32x2) ---------
// Output transposed: g_Mt[p*32+k][bt].
__global__ void __launch_bounds__(288) k_moment(const float* __restrict__ X) {
    __shared__ __align__(16) float2 Xc[2][8][36];
    __shared__ __align__(16) float2 ACs[2][256];

    int bt  = blockIdx.x;
    int tid = threadIdx.x;
    int k   = tid & 31;
    int pg  = tid >> 5;           // 0..8
    int ffl = tid / 36;           // 0..7 (288 = 8*36 exactly)
    int pl  = tid - ffl * 36;
    const float* Xb = X + (size_t)bt * (F_BINS * 72);
    unsigned long long p0 = 0, p1 = 0, p2 = 0, p3 = 0;

    // prefetch chunk 0
    float re = Xb[ffl*72 + pl];
    float im = Xb[ffl*72 + 36 + pl];
    float2 cs = make_float2(0.f, 0.f);
    if (tid < 256) cs = g_CS[tid];

    for (int c = 0; c < 64; c++) {     // 64 full chunks of 8 freqs
        int buf = c & 1;
        float s   = fmaf(re, re, im * im);
        float inv = rsqrtf(fmaxf(s, 1e-36f));
        Xc[buf][ffl][pl] = make_float2(re * inv, im * inv);
        if (tid < 256) ACs[buf][tid] = cs;
        __syncthreads();
        // prefetch chunk c+1 (c=63 prefetches the 1-freq tail)
        {
            int f0n = (c + 1) * 8;
            int nfn = F_BINS - f0n; if (nfn > 8) nfn = 8;
            if (ffl < nfn) {
                re = Xb[(f0n + ffl)*72 + pl];
                im = Xb[(f0n + ffl)*72 + 36 + pl];
            }
            if (tid < nfn * 32) cs = g_CS[f0n*32 + tid];
        }
#pragma unroll
        for (int ff = 0; ff < 8; ff++) {
            unsigned long long acas = *(const unsigned long long*)&ACs[buf][ff*32 + k];
            ulonglong2 xa = *(const ulonglong2*)&Xc[buf][ff][pg*4];
            ulonglong2 xb = *(const ulonglong2*)&Xc[buf][ff][pg*4 + 2];
            fma2(p0, xa.x, acas);
            fma2(p1, xa.y, acas);
            fma2(p2, xb.x, acas);
            fma2(p3, xb.y, acas);
        }
    }
    // tail chunk: f = 512 only (buf 0; chunk 63 used buf 1)
    {
        if (ffl < 1) {
            float s   = fmaf(re, re, im * im);
            float inv = rsqrtf(fmaxf(s, 1e-36f));
            Xc[0][0][pl] = make_float2(re * inv, im * inv);
        }
        if (tid < 32) ACs[0][tid] = cs;
        __syncthreads();
        unsigned long long acas = *(const unsigned long long*)&ACs[0][k];
        ulonglong2 xa = *(const ulonglong2*)&Xc[0][0][pg*4];
        ulonglong2 xb = *(const ulonglong2*)&Xc[0][0][pg*4 + 2];
        fma2(p0, xa.x, acas);
        fma2(p1, xa.y, acas);
        fma2(p2, xb.x, acas);
        fma2(p3, xb.y, acas);
    }
    float* Mo = g_Mt + bt;
    Mo[(size_t)((pg*4 + 0)*32 + k) * BT_PAD] = plo(p0) + phi(p0);
    Mo[(size_t)((pg*4 + 1)*32 + k) * BT_PAD] = plo(p1) + phi(p1);
    Mo[(size_t)((pg*4 + 2)*32 + k) * BT_PAD] = plo(p2) + phi(p2);
    Mo[(size_t)((pg*4 + 3)*32 + k) * BT_PAD] = plo(p3) + phi(p3);
}

// ---------------- Stage C: Ys = M^T(K-major) x W^T, FFMA2 + cp.async pipeline --
// 128(m) x 64(d) tile, 256 threads, 3 blocks/SM, double-buffered smem via
// cp.async (no STS, no prefetch registers). K-major global layout: no transpose.
#define KC 32
#define BM 128
#define BD 64
#define NCH (PK / KC)   // 36 chunks
__global__ void __launch_bounds__(256, 3) k_gemm() {
    __shared__ __align__(16) float Ms[2][KC][BM];   // 2*16KB
    __shared__ __align__(16) float Ws[2][KC][BD];   // 2*8KB  (total 48KB)
    int d0 = blockIdx.x * BD;
    int m0 = blockIdx.y * BM;
    int tid = threadIdx.x;
    int tx = tid & 15, ty = tid >> 4;     // consumer: d=tx*4, m=ty*8
    unsigned long long acc[4][4] = {};    // [m-pair][d]

    // chunk loader: Ms = 1024 16B-chunks (4/thread), Ws = 512 (2/thread)
    const float* MgBase = g_Mt + m0;
    const float* WgBase = g_Wt + d0;

#define LOAD_CHUNK(buf, k0)                                                     \
    {                                                                           \
        _Pragma("unroll")                                                       \
        for (int i = 0; i < 4; i++) {                                           \
            int idx = tid + 256*i;                                              \
            int r = idx >> 5, c16 = idx & 31;                                   \
            cp16(&Ms[buf][r][c16*4], MgBase + (size_t)((k0) + r) * BT_PAD + c16*4); \
        }                                                                       \
        _Pragma("unroll")                                                       \
        for (int i = 0; i < 2; i++) {                                           \
            int idx = tid + 256*i;                                              \
            int r = idx >> 4, c16 = idx & 15;                                   \
            cp16(&Ws[buf][r][c16*4], WgBase + (size_t)((k0) + r) * D_PAD + c16*4);  \
        }                                                                       \
        CP_COMMIT();                                                            \
    }

    LOAD_CHUNK(0, 0);
    for (int c = 0; c < NCH; c++) {
        int buf = c & 1;
        if (c + 1 < NCH) {
            LOAD_CHUNK(buf ^ 1, (c + 1) * KC);
            CP_WAIT(1);
        } else {
            CP_WAIT(0);
        }
        __syncthreads();
#pragma unroll
        for (int kk = 0; kk < KC; kk++) {
            float4 bq = *(const float4*)&Ws[buf][kk][tx*4];
            ulonglong2 a01 = *(const ulonglong2*)&Ms[buf][kk][ty*8];
            ulonglong2 a23 = *(const ulonglong2*)&Ms[buf][kk][ty*8 + 4];
            unsigned long long pb0, pb1, pb2, pb3;
            PACKDUP(pb0, bq.x);
            PACKDUP(pb1, bq.y);
            PACKDUP(pb2, bq.z);
            PACKDUP(pb3, bq.w);
            fma2(acc[0][0], a01.x, pb0); fma2(acc[0][1], a01.x, pb1);
            fma2(acc[0][2], a01.x, pb2); fma2(acc[0][3], a01.x, pb3);
            fma2(acc[1][0], a01.y, pb0); fma2(acc[1][1], a01.y, pb1);
            fma2(acc[1][2], a01.y, pb2); fma2(acc[1][3], a01.y, pb3);
            fma2(acc[2][0], a23.x, pb0); fma2(acc[2][1], a23.x, pb1);
            fma2(acc[2][2], a23.x, pb2); fma2(acc[2][3], a23.x, pb3);
            fma2(acc[3][0], a23.y, pb0); fma2(acc[3][1], a23.y, pb1);
            fma2(acc[3][2], a23.y, pb2); fma2(acc[3][3], a23.y, pb3);
        }
        __syncthreads();
    }
#pragma unroll
    for (int mp = 0; mp < 4; mp++) {
        float4 vlo = make_float4(plo(acc[mp][0]), plo(acc[mp][1]),
                                 plo(acc[mp][2]), plo(acc[mp][3]));
        float4 vhi = make_float4(phi(acc[mp][0]), phi(acc[mp][1]),
                                 phi(acc[mp][2]), phi(acc[mp][3]));
        *(float4*)(g_Y + (size_t)(m0 + ty*8 + 2*mp + 0) * YP + d0 + tx*4) = vlo;
        *(float4*)(g_Y + (size_t)(m0 + ty*8 + 2*mp + 1) * YP + d0 + tx*4) = vhi;
    }
#undef LOAD_CHUNK
}

// ---------------- Stage D: argmax over D + gather doas -------------------------
__global__ void __launch_bounds__(256) k_argmax(const float* __restrict__ doas,
                                                float* __restrict__ out, int D) {
    __shared__ float sv[256];
    __shared__ int   si[256];
    int bt = blockIdx.x, tid = threadIdx.x;
    const float* y = g_Y + (size_t)bt * YP;
    float bv = -3.4e38f; int bi = 0;
    for (int d = tid; d < D; d += 256) {
        float v = y[d];
        if (v > bv) { bv = v; bi = d; }
    }
    sv[tid] = bv; si[tid] = bi;
    __syncthreads();
    for (int s = 128; s > 0; s >>= 1) {
        if (tid < s) {
            float v2 = sv[tid + s]; int i2 = si[tid + s];
            if (v2 > sv[tid] || (v2 == sv[tid] && i2 < si[tid])) { sv[tid] = v2; si[tid] = i2; }
        }
        __syncthreads();
    }
    if (tid < 3) out[bt*3 + tid] = doas[si[0]*3 + tid];
}

// ---------------- launch -------------------------------------------------------
extern "C" void kernel_launch(void* const* d_in, const int* in_sizes, int n_in,
                              void* d_out, int out_size) {
    const float* XXs  = (const float*)d_in[0];
    const float* taus = (const float*)d_in[1];
    const float* doas = (const float*)d_in[2];
    float* out = (float*)d_out;

    int D  = in_sizes[1] / 8;            if (D  > D_PTS) D  = D_PTS;
    int BT = in_sizes[0] / (F_BINS*72);  if (BT > BT_N)  BT = BT_N;

    k_coeff<<<F_BINS, 64>>>();
    k_w2t<<<(D_PAD + 127) / 128, 128>>>(taus, D);
    k_moment<<<BT, 288>>>(XXs);
    dim3 g(D_PAD / BD, (BT + BM - 1) / BM);
    k_gemm<<<g, 256>>>();
    k_argmax<<<BT, 256>>>(doas, out, D);
}

// round 14
// speedup vs baseline: 1.5310x; 1.5310x over previous
#include <cuda_runtime.h>
#include <math.h>

#define D_PTS   2562
#define D_PAD   2624          // 41*64
#define NDB     41            // d-blocks in gemm grid
#define F_BINS  513
#define P_PAIRS 36
#define KDEG    32
#define PK      (P_PAIRS*KDEG)   // 1152
#define BT_N    1000
#define BT_PAD  1024
#define TAU_M   4.67

// ---------------- packed f32x2 helpers ----------------------------------------
__device__ __forceinline__ void fma2(unsigned long long& d,
                                     unsigned long long a, unsigned long long b) {
    asm("fma.rn.f32x2 %0, %1, %2, %0;" : "+l"(d) : "l"(a), "l"(b));
}
__device__ __forceinline__ float plo(unsigned long long v) {
    return __uint_as_float((unsigned)v);
}
__device__ __forceinline__ float phi(unsigned long long v) {
    return __uint_as_float((unsigned)(v >> 32));
}
#define PACKDUP(out, v) asm("mov.b64 %0, {%1, %1};" : "=l"(out) : "f"(v))

// ---------------- scratch ------------------------------------------------------
__device__ float2 g_CS[F_BINS*KDEG];         // (ac,as) packed per (f,k)
__device__ float  g_M[(size_t)BT_PAD*PK];    // moments   [bt][p*32+k]
__device__ float  g_W[(size_t)D_PAD*PK];     // Cheb vals [d][p*32+k]
__device__ float  g_pV[(size_t)BT_PAD*NDB];  // partial max val [bt][dblock]
__device__ int    g_pI[(size_t)BT_PAD*NDB];  // partial max idx

__device__ const int c_i0[P_PAIRS] = {0,0,0,0,0,0,0,0, 1,1,1,1,1,1,1, 2,2,2,2,2,2,
                                      3,3,3,3,3, 4,4,4,4, 5,5,5, 6,6, 7};
__device__ const int c_i1[P_PAIRS] = {0,1,2,3,4,5,6,7, 1,2,3,4,5,6,7, 2,3,4,5,6,7,
                                      3,4,5,6,7, 4,5,6,7, 5,6,7, 6,7, 7};

// ---------------- Stage A1: Chebyshev coefficients (fp64 DCT) ------------------
__global__ void k_coeff() {
    __shared__ double vc[64], vs[64];
    const double PI = 3.141592653589793238462643;
    int f = blockIdx.x;
    int n = threadIdx.x;
    double c = (2.0 * PI * (double)f / 1024.0) * (double)TAU_M;
    double theta = PI * (n + 0.5) / 64.0;
    double x = cos(theta);
    double sn, cn;
    sincos(c * x, &sn, &cn);
    vc[n] = cn; vs[n] = sn;
    __syncthreads();
    int k = threadIdx.x;
    if (k < KDEG) {
        double delta = (PI / 64.0) * (double)k;
        double c0 = cos(0.5 * delta);
        double c1 = cos(1.5 * delta);
        double mult = 2.0 * cos(delta);
        double sc = vc[0]*c0 + vc[1]*c1;
        double ss = vs[0]*c0 + vs[1]*c1;
        double cp = c0, cc = c1;
        for (int nn = 2; nn < 64; nn++) {
            double cnx = mult*cc - cp;
            sc += vc[nn]*cnx; ss += vs[nn]*cnx;
            cp = cc; cc = cnx;
        }
        double scale = (k == 0 ? 1.0 : 2.0) / 64.0;
        g_CS[f*KDEG + k] = make_float2((float)(sc*scale), (float)(ss*scale));
    }
}

// ---------------- Stage A2: T_k(u_{d,p}) table --------------------------------
__global__ void k_w2(const float* __restrict__ taus, int D) {
    int idx = blockIdx.x * blockDim.x + threadIdx.x;
    if (idx >= D * P_PAIRS) return;
    int d = idx / P_PAIRS, p = idx - d * P_PAIRS;
    float u = (taus[d*8 + c_i0[p]] - taus[d*8 + c_i1[p]]) * (float)(1.0 / TAU_M);
    float* w = g_W + (size_t)d * PK + p * KDEG;
    float tp = 1.0f, tc = u;
    w[0] = 1.0f; w[1] = u;
    float u2 = 2.0f * u;
#pragma unroll
    for (int kk = 2; kk < KDEG; kk++) {
        float tn = fmaf(u2, tc, -tp);
        w[kk] = tn; tp = tc; tc = tn;
    }
}

// ---------------- Stage B: PHAT normalize + moments (16-freq chunks, f32x2) ----
// One barrier per 16 freqs; next chunk prefetched in registers; double-buffered.
__global__ void __launch_bounds__(288) k_moment(const float* __restrict__ X) {
    __shared__ __align__(16) float2 Xc[2][16][36];
    __shared__ __align__(16) float2 ACs[2][512];

    int bt  = blockIdx.x;
    int tid = threadIdx.x;
    int k   = tid & 31;
    int pg  = tid >> 5;           // warp id 0..8
    int ffl = tid / 36;           // 0..7
    int pl  = tid - ffl * 36;
    const float* Xb = X + (size_t)bt * (F_BINS * 72);
    unsigned long long p0 = 0, p1 = 0, p2 = 0, p3 = 0;

    float re[2], im[2];
    float2 cs[2];
    // prefetch chunk 0 (freqs 0..15)
#pragma unroll
    for (int h = 0; h < 2; h++) {
        int ff = ffl + 8*h;
        re[h] = Xb[ff*72 + pl];
        im[h] = Xb[ff*72 + 36 + pl];
    }
    cs[0] = g_CS[tid];
    cs[1] = (tid < 224) ? g_CS[tid + 288] : make_float2(0.f, 0.f);

    for (int c = 0; c < 32; c++) {     // 32 chunks of 16 freqs
        int buf = c & 1;
#pragma unroll
        for (int h = 0; h < 2; h++) {
            float s   = fmaf(re[h], re[h], im[h] * im[h]);
            float inv = rsqrtf(fmaxf(s, 1e-36f));
            Xc[buf][ffl + 8*h][pl] = make_float2(re[h] * inv, im[h] * inv);
        }
        ACs[buf][tid] = cs[0];
        if (tid < 224) ACs[buf][tid + 288] = cs[1];
        __syncthreads();
        // prefetch chunk c+1 (c=31 prefetches the 1-freq tail)
        {
            int f0n = (c + 1) * 16;
            int nfn = F_BINS - f0n; if (nfn > 16) nfn = 16;
#pragma unroll
            for (int h = 0; h < 2; h++) {
                int ff = ffl + 8*h;
                if (ff < nfn) {
                    re[h] = Xb[(f0n + ff)*72 + pl];
                    im[h] = Xb[(f0n + ff)*72 + 36 + pl];
                }
            }
            if (tid < nfn * 32)        cs[0] = g_CS[f0n*32 + tid];
            if (tid + 288 < nfn * 32)  cs[1] = g_CS[f0n*32 + tid + 288];
        }
#pragma unroll
        for (int ff = 0; ff < 16; ff++) {
            unsigned long long acas = *(const unsigned long long*)&ACs[buf][ff*32 + k];
            ulonglong2 xa = *(const ulonglong2*)&Xc[buf][ff][pg*4];
            ulonglong2 xb = *(const ulonglong2*)&Xc[buf][ff][pg*4 + 2];
            fma2(p0, xa.x, acas);
            fma2(p1, xa.y, acas);
            fma2(p2, xb.x, acas);
            fma2(p3, xb.y, acas);
        }
    }
    // tail chunk: f = 512 only (buf 0; chunk 31 used buf 1)
    {
        if (ffl == 0) {
            float s   = fmaf(re[0], re[0], im[0] * im[0]);
            float inv = rsqrtf(fmaxf(s, 1e-36f));
            Xc[0][0][pl] = make_float2(re[0] * inv, im[0] * inv);
        }
        if (tid < 32) ACs[0][tid] = cs[0];
        __syncthreads();
        unsigned long long acas = *(const unsigned long long*)&ACs[0][k];
        ulonglong2 xa = *(const ulonglong2*)&Xc[0][0][pg*4];
        ulonglong2 xb = *(const ulonglong2*)&Xc[0][0][pg*4 + 2];
        fma2(p0, xa.x, acas);
        fma2(p1, xa.y, acas);
        fma2(p2, xb.x, acas);
        fma2(p3, xb.y, acas);
    }
    float* Mo = g_M + (size_t)bt * PK + k;
    Mo[(pg*4 + 0)*32] = plo(p0) + phi(p0);
    Mo[(pg*4 + 1)*32] = plo(p1) + phi(p1);
    Mo[(pg*4 + 2)*32] = plo(p2) + phi(p2);
    Mo[(pg*4 + 3)*32] = plo(p3) + phi(p3);
}

// ---------------- Stage C: gemm (R8 mainloop) + fused partial argmax -----------
// 128(m) x 64(d) tile, 256 threads, 8x4 microtile as 4 packed m-pairs x 4 d.
// Epilogue: per-row max over the 64-d tile via shuffle; writes (val,idx) partial.
#define KC 32
#define BM 128
#define BD 64
__global__ void __launch_bounds__(256) k_gemm(int D) {
    __shared__ __align__(16) float Ms[KC][BM+4];  // [k][m], stride 132
    __shared__ __align__(16) float Ws[KC][BD+4];  // [k][d], stride 68
    int d0 = blockIdx.x * BD;
    int m0 = blockIdx.y * BM;
    int tid = threadIdx.x;
    int tx = tid & 15, ty = tid >> 4;     // consumer: d=tx*4, m=ty*8
    int lk = (tid & 7) * 4;               // loader k offset 0..28
    int lr = tid >> 3;                    // loader row 0..31
    const float* Mg = g_M + (size_t)(m0 + lr) * PK + lk;
    const float* Wg = g_W + (size_t)(d0 + lr) * PK + lk;
    unsigned long long acc[4][4] = {};    // [m-pair][d]

    float4 mpre[4], wpre[2];
#pragma unroll
    for (int i = 0; i < 4; i++) mpre[i] = *(const float4*)(Mg + (size_t)32*i*PK);
#pragma unroll
    for (int i = 0; i < 2; i++) wpre[i] = *(const float4*)(Wg + (size_t)32*i*PK);

    for (int k0 = 0; k0 < PK; k0 += KC) {
#pragma unroll
        for (int i = 0; i < 4; i++) {
            Ms[lk+0][lr+32*i] = mpre[i].x;
            Ms[lk+1][lr+32*i] = mpre[i].y;
            Ms[lk+2][lr+32*i] = mpre[i].z;
            Ms[lk+3][lr+32*i] = mpre[i].w;
        }
#pragma unroll
        for (int i = 0; i < 2; i++) {
            Ws[lk+0][lr+32*i] = wpre[i].x;
            Ws[lk+1][lr+32*i] = wpre[i].y;
            Ws[lk+2][lr+32*i] = wpre[i].z;
            Ws[lk+3][lr+32*i] = wpre[i].w;
        }
        __syncthreads();
        if (k0 + KC < PK) {
#pragma unroll
            for (int i = 0; i < 4; i++) mpre[i] = *(const float4*)(Mg + k0 + KC + (size_t)32*i*PK);
#pragma unroll
            for (int i = 0; i < 2; i++) wpre[i] = *(const float4*)(Wg + k0 + KC + (size_t)32*i*PK);
        }
#pragma unroll
        for (int kk = 0; kk < KC; kk++) {
            float4 bq = *(const float4*)&Ws[kk][tx*4];
            ulonglong2 a01 = *(const ulonglong2*)&Ms[kk][ty*8];
            ulonglong2 a23 = *(const ulonglong2*)&Ms[kk][ty*8 + 4];
            unsigned long long pb0, pb1, pb2, pb3;
            PACKDUP(pb0, bq.x);
            PACKDUP(pb1, bq.y);
            PACKDUP(pb2, bq.z);
            PACKDUP(pb3, bq.w);
            fma2(acc[0][0], a01.x, pb0); fma2(acc[0][1], a01.x, pb1);
            fma2(acc[0][2], a01.x, pb2); fma2(acc[0][3], a01.x, pb3);
            fma2(acc[1][0], a01.y, pb0); fma2(acc[1][1], a01.y, pb1);
            fma2(acc[1][2], a01.y, pb2); fma2(acc[1][3], a01.y, pb3);
            fma2(acc[2][0], a23.x, pb0); fma2(acc[2][1], a23.x, pb1);
            fma2(acc[2][2], a23.x, pb2); fma2(acc[2][3], a23.x, pb3);
            fma2(acc[3][0], a23.y, pb0); fma2(acc[3][1], a23.y, pb1);
            fma2(acc[3][2], a23.y, pb2); fma2(acc[3][3], a23.y, pb3);
        }
        __syncthreads();
    }

    // ---- fused partial argmax over this 64-d tile (tie: lowest d wins) ----
    int dbase = d0 + tx*4;
#pragma unroll
    for (int mp = 0; mp < 4; mp++) {
#pragma unroll
        for (int h = 0; h < 2; h++) {
            float v[4];
            v[0] = h ? phi(acc[mp][0]) : plo(acc[mp][0]);
            v[1] = h ? phi(acc[mp][1]) : plo(acc[mp][1]);
            v[2] = h ? phi(acc[mp][2]) : plo(acc[mp][2]);
            v[3] = h ? phi(acc[mp][3]) : plo(acc[mp][3]);
            float bv = -3.4e38f; int bi = 0;
#pragma unroll
            for (int j = 0; j < 4; j++) {
                int dd = dbase + j;
                float vv = (dd < D) ? v[j] : -3.4e38f;
                if (vv > bv) { bv = vv; bi = dd; }
            }
#pragma unroll
            for (int msk = 1; msk < 16; msk <<= 1) {
                float ov = __shfl_xor_sync(0xFFFFFFFFu, bv, msk);
                int   oi = __shfl_xor_sync(0xFFFFFFFFu, bi, msk);
                if (ov > bv || (ov == bv && oi < bi)) { bv = ov; bi = oi; }
            }
            if (tx == 0) {
                int row = m0 + ty*8 + 2*mp + h;
                g_pV[(size_t)row * NDB + blockIdx.x] = bv;
                g_pI[(size_t)row * NDB + blockIdx.x] = bi;
            }
        }
    }
}

// ---------------- Stage D: reduce 41 partials per bt + gather doas -------------
__global__ void __launch_bounds__(256) k_red(const float* __restrict__ doas,
                                             float* __restrict__ out, int BT) {
    int bt = blockIdx.x * 256 + threadIdx.x;
    if (bt >= BT) return;
    float bv = -3.4e38f; int bi = 0;
#pragma unroll
    for (int b = 0; b < NDB; b++) {
        float v = g_pV[(size_t)bt * NDB + b];
        int   i = g_pI[(size_t)bt * NDB + b];
        if (v > bv || (v == bv && i < bi)) { bv = v; bi = i; }
    }
    out[bt*3 + 0] = doas[bi*3 + 0];
    out[bt*3 + 1] = doas[bi*3 + 1];
    out[bt*3 + 2] = doas[bi*3 + 2];
}

// ---------------- launch -------------------------------------------------------
extern "C" void kernel_launch(void* const* d_in, const int* in_sizes, int n_in,
                              void* d_out, int out_size) {
    const float* XXs  = (const float*)d_in[0];
    const float* taus = (const float*)d_in[1];
    const float* doas = (const float*)d_in[2];
    float* out = (float*)d_out;

    int D  = in_sizes[1] / 8;            if (D  > D_PTS) D  = D_PTS;
    int BT = in_sizes[0] / (F_BINS*72);  if (BT > BT_N)  BT = BT_N;

    k_coeff<<<F_BINS, 64>>>();
    k_w2<<<(D * P_PAIRS + 255) / 256, 256>>>(taus, D);
    k_moment<<<BT, 288>>>(XXs);
    dim3 g(NDB, (BT + BM - 1) / BM);
    k_gemm<<<g, 256>>>(D);
    k_red<<<(BT + 255) / 256, 256>>>(doas, out, BT);
}